// round 5
// baseline (speedup 1.0000x reference)
#include <cuda_runtime.h>
#include <math.h>

#define NN 8192
#define KNB 16
#define DD 256
#define EE 128
#define HH 512
#define OO 256

// ---- scratch (no allocations allowed; __device__ globals) ----
__device__ float g_h1[NN * HH];     // tanh(x @ W1x^T)
__device__ float g_xatt[NN * HH];   // x_att
__device__ float g_yn[NN * HH];     // x_att @ W2n
__device__ float g_ye[NN * HH];     // x_att @ W2e
__device__ float g_wsn[NN * KNB];   // raw neib logits
__device__ float g_wse[NN * KNB];   // raw edge logits
__device__ float g_aggn[NN * DD];
__device__ float g_agge[NN * EE];

// ============================================================
// Generic fp32 tiled GEMM: C[M,Nc] = act(A[M,Kc] @ op(B))
//   TRANSB: B is [Nc,Kc] (torch weight layout), else B is [Kc,Nc]
//   TANH: apply tanh; BIASRELU: add bias[col] then relu
// Requires: M%128==0, Nc%128==0, Kc%16==0 (true for all shapes here)
// ============================================================
template<bool TRANSB, bool TANH, bool BIASRELU>
__global__ void __launch_bounds__(256)
gemm_kernel(const float* __restrict__ A, const float* __restrict__ B,
            const float* __restrict__ bias, float* __restrict__ C,
            int M, int Nc, int Kc, int ldc, int coff)
{
    __shared__ float As[16][128];
    __shared__ float Bs[16][128];
    const int tid = threadIdx.x;
    const int tx = tid & 15, ty = tid >> 4;
    const int m0 = blockIdx.y * 128;
    const int n0 = blockIdx.x * 128;

    const int ar = tid >> 2;        // 0..63
    const int ac = (tid & 3) * 4;   // 0,4,8,12

    float acc[8][8] = {};

    for (int k0 = 0; k0 < Kc; k0 += 16) {
        // load A tile (rows m0.., k-cols k0..k0+15), transposed into As[k][m]
        #pragma unroll
        for (int r = 0; r < 2; r++) {
            int row = ar + r * 64;
            float4 v = *(const float4*)(A + (size_t)(m0 + row) * Kc + k0 + ac);
            As[ac + 0][row] = v.x; As[ac + 1][row] = v.y;
            As[ac + 2][row] = v.z; As[ac + 3][row] = v.w;
        }
        // load B tile into Bs[k][n]
        if (TRANSB) {
            #pragma unroll
            for (int r = 0; r < 2; r++) {
                int row = ar + r * 64;
                float4 v = *(const float4*)(B + (size_t)(n0 + row) * Kc + k0 + ac);
                Bs[ac + 0][row] = v.x; Bs[ac + 1][row] = v.y;
                Bs[ac + 2][row] = v.z; Bs[ac + 3][row] = v.w;
            }
        } else {
            int kr = tid >> 5;         // 0..7
            int nc = (tid & 31) * 4;   // 0..124
            #pragma unroll
            for (int r = 0; r < 2; r++) {
                int krr = kr + r * 8;
                float4 v = *(const float4*)(B + (size_t)(k0 + krr) * Nc + n0 + nc);
                *(float4*)&Bs[krr][nc] = v;
            }
        }
        __syncthreads();
        #pragma unroll
        for (int kk = 0; kk < 16; kk++) {
            float af[8], bf[8];
            *(float4*)&af[0] = *(const float4*)&As[kk][ty * 8];
            *(float4*)&af[4] = *(const float4*)&As[kk][ty * 8 + 4];
            *(float4*)&bf[0] = *(const float4*)&Bs[kk][tx * 8];
            *(float4*)&bf[4] = *(const float4*)&Bs[kk][tx * 8 + 4];
            #pragma unroll
            for (int i = 0; i < 8; i++)
                #pragma unroll
                for (int j = 0; j < 8; j++)
                    acc[i][j] = fmaf(af[i], bf[j], acc[i][j]);
        }
        __syncthreads();
    }

    // epilogue
    #pragma unroll
    for (int i = 0; i < 8; i++) {
        int row = m0 + ty * 8 + i;
        #pragma unroll
        for (int jv = 0; jv < 2; jv++) {
            float4 v;
            float* vv = (float*)&v;
            #pragma unroll
            for (int j = 0; j < 4; j++) {
                int col = tx * 8 + jv * 4 + j;
                float val = acc[i][jv * 4 + j];
                if (TANH) val = tanhf(val);
                if (BIASRELU) { val += bias[n0 + col]; val = fmaxf(val, 0.0f); }
                vv[j] = val;
            }
            *(float4*)(C + (size_t)row * ldc + coff + n0 + tx * 8 + jv * 4) = v;
        }
    }
}

// ============================================================
// Fused logit kernel:
//   ws[m] = sum_h tanh( A[m,:] @ W1[h,:] ) * y[m/16, h]     (h = 0..511)
// A: [131072, KD]  W1: [512, KD]  y: [8192, 512]  ws: [131072]
// One block = 128 rows; loops over 4 column chunks of H.
// ============================================================
template<int KD>
__global__ void __launch_bounds__(256)
ws_kernel(const float* __restrict__ A, const float* __restrict__ W1,
          const float* __restrict__ y, float* __restrict__ ws)
{
    __shared__ float As[16][128];
    __shared__ float Bs[16][128];
    __shared__ float ys[8 * 128];
    __shared__ float red[128][16];

    const int tid = threadIdx.x;
    const int tx = tid & 15, ty = tid >> 4;
    const int m0 = blockIdx.x * 128;
    const int node0 = m0 >> 4;          // 8 nodes per block
    const int ar = tid >> 2;
    const int ac = (tid & 3) * 4;

    float wsacc[8] = {};

    for (int hc = 0; hc < 4; hc++) {
        const int h0 = hc * 128;
        // y tile: 8 nodes x 128 h-values (1024 floats, one float4 per thread)
        {
            int nl = tid >> 5;           // 0..7
            int hh = (tid & 31) * 4;
            *(float4*)&ys[nl * 128 + hh] =
                *(const float4*)(y + (size_t)(node0 + nl) * HH + h0 + hh);
        }
        float acc[8][8] = {};
        for (int k0 = 0; k0 < KD; k0 += 16) {
            #pragma unroll
            for (int r = 0; r < 2; r++) {
                int row = ar + r * 64;
                float4 v = *(const float4*)(A + (size_t)(m0 + row) * KD + k0 + ac);
                As[ac + 0][row] = v.x; As[ac + 1][row] = v.y;
                As[ac + 2][row] = v.z; As[ac + 3][row] = v.w;
                float4 w = *(const float4*)(W1 + (size_t)(h0 + row) * KD + k0 + ac);
                Bs[ac + 0][row] = w.x; Bs[ac + 1][row] = w.y;
                Bs[ac + 2][row] = w.z; Bs[ac + 3][row] = w.w;
            }
            __syncthreads();
            #pragma unroll
            for (int kk = 0; kk < 16; kk++) {
                float af[8], bf[8];
                *(float4*)&af[0] = *(const float4*)&As[kk][ty * 8];
                *(float4*)&af[4] = *(const float4*)&As[kk][ty * 8 + 4];
                *(float4*)&bf[0] = *(const float4*)&Bs[kk][tx * 8];
                *(float4*)&bf[4] = *(const float4*)&Bs[kk][tx * 8 + 4];
                #pragma unroll
                for (int i = 0; i < 8; i++)
                    #pragma unroll
                    for (int j = 0; j < 8; j++)
                        acc[i][j] = fmaf(af[i], bf[j], acc[i][j]);
            }
            __syncthreads();
        }
        // epilogue: tanh then dot with y
        #pragma unroll
        for (int i = 0; i < 8; i++) {
            int rl = ty * 8 + i;
            int nl = rl >> 4;
            float s = 0.0f;
            #pragma unroll
            for (int j = 0; j < 8; j++)
                s = fmaf(tanhf(acc[i][j]), ys[nl * 128 + tx * 8 + j], s);
            wsacc[i] += s;
        }
        __syncthreads();   // protect ys/As before next chunk overwrites
    }

    // cross-thread (tx) reduction of per-row partials
    #pragma unroll
    for (int i = 0; i < 8; i++)
        red[ty * 8 + i][tx] = wsacc[i];
    __syncthreads();
    if (tid < 128) {
        float s = 0.0f;
        #pragma unroll
        for (int t = 0; t < 16; t++) s += red[tid][t];
        ws[m0 + tid] = s;
    }
}

// ============================================================
// Softmax (scaled / masked) + weighted aggregation
// ============================================================
__global__ void __launch_bounds__(128)
softmax_agg(const float* __restrict__ wsn, const float* __restrict__ wse,
            const int* __restrict__ mask, const float* __restrict__ neibs,
            const float* __restrict__ edges,
            float* __restrict__ aggn, float* __restrict__ agge)
{
    const int n = blockIdx.x;
    const int tid = threadIdx.x;
    __shared__ float s1[16], s2[16];
    if (tid < 16) {
        s1[tid] = wsn[n * 16 + tid] * 0.04419417382415922f;  // 1/sqrt(512)
        s2[tid] = wse[n * 16 + tid] - 9999999.0f * (float)mask[n * 16 + tid];
    }
    __syncthreads();

    float w1[16], w2[16];
    float m1 = -1e30f, m2 = -1e30f;
    #pragma unroll
    for (int k = 0; k < 16; k++) {
        m1 = fmaxf(m1, s1[k]);
        m2 = fmaxf(m2, s2[k]);
    }
    float t1 = 0.0f, t2 = 0.0f;
    #pragma unroll
    for (int k = 0; k < 16; k++) {
        w1[k] = expf(s1[k] - m1); t1 += w1[k];
        w2[k] = expf(s2[k] - m2); t2 += w2[k];
    }
    const float r1 = 1.0f / t1, r2 = 1.0f / t2;

    #pragma unroll
    for (int p = 0; p < 2; p++) {
        int d = tid + p * 128;
        float acc = 0.0f;
        #pragma unroll
        for (int k = 0; k < 16; k++)
            acc = fmaf(w1[k], neibs[((size_t)n * 16 + k) * DD + d], acc);
        aggn[(size_t)n * DD + d] = acc * r1;
    }
    {
        int d = tid;
        float acc = 0.0f;
        #pragma unroll
        for (int k = 0; k < 16; k++)
            acc = fmaf(w2[k], edges[((size_t)n * 16 + k) * EE + d], acc);
        agge[(size_t)n * EE + d] = acc * r2;
    }
}

// ============================================================
extern "C" void kernel_launch(void* const* d_in, const int* in_sizes, int n_in,
                              void* d_out, int out_size)
{
    const float* x     = (const float*)d_in[0];
    const float* neibs = (const float*)d_in[1];
    const float* edge  = (const float*)d_in[2];
    const int*   mask  = (const int*)  d_in[3];
    const float* W1x   = (const float*)d_in[4];
    const float* W2x   = (const float*)d_in[5];
    const float* W1n   = (const float*)d_in[6];
    const float* W2n   = (const float*)d_in[7];
    const float* W1e   = (const float*)d_in[8];
    const float* W2e   = (const float*)d_in[9];
    const float* Wfx   = (const float*)d_in[10];
    const float* bfx   = (const float*)d_in[11];
    const float* Wfn   = (const float*)d_in[12];
    const float* bfn   = (const float*)d_in[13];
    const float* Wfe   = (const float*)d_in[14];
    const float* bfe   = (const float*)d_in[15];
    float* out = (float*)d_out;

    float *h1, *xatt, *yn, *ye, *wsn, *wse, *aggn, *agge;
    cudaGetSymbolAddress((void**)&h1,   g_h1);
    cudaGetSymbolAddress((void**)&xatt, g_xatt);
    cudaGetSymbolAddress((void**)&yn,   g_yn);
    cudaGetSymbolAddress((void**)&ye,   g_ye);
    cudaGetSymbolAddress((void**)&wsn,  g_wsn);
    cudaGetSymbolAddress((void**)&wse,  g_wse);
    cudaGetSymbolAddress((void**)&aggn, g_aggn);
    cudaGetSymbolAddress((void**)&agge, g_agge);

    dim3 blk(256);

    // x_att pipeline (8192 rows)
    gemm_kernel<true,  true,  false><<<dim3(HH/128, NN/128), blk>>>(x,    W1x, nullptr, h1,   NN, HH, DD, HH, 0);
    gemm_kernel<true,  false, false><<<dim3(HH/128, NN/128), blk>>>(h1,   W2x, nullptr, xatt, NN, HH, HH, HH, 0);
    // y_n = x_att @ W2n ; y_e = x_att @ W2e   (B not transposed)
    gemm_kernel<false, false, false><<<dim3(HH/128, NN/128), blk>>>(xatt, W2n, nullptr, yn,   NN, HH, HH, HH, 0);
    gemm_kernel<false, false, false><<<dim3(HH/128, NN/128), blk>>>(xatt, W2e, nullptr, ye,   NN, HH, HH, HH, 0);

    // attention logits (the heavy part: 131072-row GEMMs fused with dot-epilogue)
    ws_kernel<DD><<<(NN * KNB) / 128, blk>>>(neibs, W1n, yn, wsn);
    ws_kernel<EE><<<(NN * KNB) / 128, blk>>>(edge,  W1e, ye, wse);

    // softmax + aggregation
    softmax_agg<<<NN, 128>>>(wsn, wse, mask, neibs, edge, aggn, agge);

    // final linears + bias + relu, written strided into [8192, 768] output
    gemm_kernel<true, false, true><<<dim3(OO/128, NN/128), blk>>>(x,    Wfx, bfx, out, NN, OO, DD, 3*OO, 0);
    gemm_kernel<true, false, true><<<dim3(OO/128, NN/128), blk>>>(aggn, Wfn, bfn, out, NN, OO, DD, 3*OO, OO);
    gemm_kernel<true, false, true><<<dim3(OO/128, NN/128), blk>>>(agge, Wfe, bfe, out, NN, OO, EE, 3*OO, 2*OO);
}

// round 8
// speedup vs baseline: 1.4474x; 1.4474x over previous
#include <cuda_runtime.h>
#include <cuda_bf16.h>
#include <mma.h>
#include <math.h>
#include <stdint.h>

using namespace nvcuda;

#define NN 8192
#define KNB 16
#define DD 256
#define EE 128
#define HH 512
#define OO 256

// ---- scratch (no allocations allowed; __device__ globals) ----
__device__ float g_h1[NN * HH];
__device__ float g_xatt[NN * HH];
__device__ float g_yn[NN * HH];
__device__ float g_ye[NN * HH];
__device__ float g_wsn[NN * KNB];
__device__ float g_wse[NN * KNB];
__device__ float g_aggn[NN * DD];
__device__ float g_agge[NN * EE];
// bf16 hi/lo splits
__device__ __nv_bfloat16 g_nhi[NN * KNB * DD];
__device__ __nv_bfloat16 g_nlo[NN * KNB * DD];
__device__ __nv_bfloat16 g_ehi[NN * KNB * EE];
__device__ __nv_bfloat16 g_elo[NN * KNB * EE];
__device__ __nv_bfloat16 g_w1nhi[HH * DD];
__device__ __nv_bfloat16 g_w1nlo[HH * DD];
__device__ __nv_bfloat16 g_w1ehi[HH * EE];
__device__ __nv_bfloat16 g_w1elo[HH * EE];

// ============================================================
// fp32 -> bf16 hi/lo split (elementwise, float4-vectorized)
// ============================================================
__global__ void __launch_bounds__(256)
split_kernel(const float* __restrict__ src, __nv_bfloat16* __restrict__ hi,
             __nv_bfloat16* __restrict__ lo, int n4)
{
    int i = blockIdx.x * blockDim.x + threadIdx.x;
    if (i >= n4) return;
    float4 v = ((const float4*)src)[i];
    __nv_bfloat162 h01 = __floats2bfloat162_rn(v.x, v.y);
    __nv_bfloat162 h23 = __floats2bfloat162_rn(v.z, v.w);
    float rx = v.x - __bfloat162float(h01.x);
    float ry = v.y - __bfloat162float(h01.y);
    float rz = v.z - __bfloat162float(h23.x);
    float rw = v.w - __bfloat162float(h23.y);
    __nv_bfloat162 l01 = __floats2bfloat162_rn(rx, ry);
    __nv_bfloat162 l23 = __floats2bfloat162_rn(rz, rw);
    uint2 ho, loo;
    ho.x  = *(uint32_t*)&h01; ho.y  = *(uint32_t*)&h23;
    loo.x = *(uint32_t*)&l01; loo.y = *(uint32_t*)&l23;
    ((uint2*)hi)[i] = ho;
    ((uint2*)lo)[i] = loo;
}

// ============================================================
// Tensor-core fused logit kernel (mma.sync via WMMA, bf16 hi/lo 3-term)
//   ws[m] = sum_h tanh( A[m,:] . W1[h,:] ) * y[m/16, h]
// Block: 128 A-rows; H processed in 8 chunks of 64; K staged in 64-chunks.
// 8 warps = 4(M) x 2(N); warp tile 32x32 = 2x2 m16n16k16 fragments.
// ============================================================
// dynamic smem (bytes):
//   [0]      As_hi 128x72 bf16 (18432)   } union with Ds 128x68 fp32 (34816)
//   [18432]  As_lo 128x72 bf16 (18432)   }
//   [36864]  Bs_hi  64x72 bf16 ( 9216)   }
//   [46080]  Bs_lo  64x72 bf16 ( 9216)   }
//   [55296]  ys 8x512 fp32 (16384)
#define WS2_SMEM 71680

template<int KD>
__global__ void __launch_bounds__(256, 2)
ws_mma(const __nv_bfloat16* __restrict__ Ahi, const __nv_bfloat16* __restrict__ Alo,
       const __nv_bfloat16* __restrict__ Whi, const __nv_bfloat16* __restrict__ Wlo,
       const float* __restrict__ y, float* __restrict__ ws)
{
    extern __shared__ char sm[];
    constexpr int KCH = KD / 64;

    __nv_bfloat16* As_hi = (__nv_bfloat16*)(sm);
    __nv_bfloat16* As_lo = (__nv_bfloat16*)(sm + 18432);
    __nv_bfloat16* Bs_hi = (__nv_bfloat16*)(sm + 36864);
    __nv_bfloat16* Bs_lo = (__nv_bfloat16*)(sm + 46080);
    float* Ds = (float*)sm;                 // union with staging
    float* ys = (float*)(sm + 55296);

    const int tid = threadIdx.x;
    const int wid = tid >> 5;
    const int m0 = blockIdx.x * 128;
    const int node0 = m0 >> 4;
    const int m_off = (wid & 3) * 32;
    const int n_off = (wid >> 2) * 32;

    // stage ys: 8 consecutive nodes x 512 = 4096 contiguous floats
    {
        const float4* src = (const float4*)(y + (size_t)node0 * HH);
        #pragma unroll
        for (int i = 0; i < 4; i++)
            ((float4*)ys)[tid + i * 256] = src[tid + i * 256];
    }

    float wsacc = 0.0f;

    for (int hc = 0; hc < 8; hc++) {
        wmma::fragment<wmma::accumulator, 16, 16, 16, float> acc[2][2];
        #pragma unroll
        for (int mi = 0; mi < 2; mi++)
            #pragma unroll
            for (int ni = 0; ni < 2; ni++)
                wmma::fill_fragment(acc[mi][ni], 0.0f);

        for (int kc = 0; kc < KCH; kc++) {
            __syncthreads();   // prior mma / epilogue reads done before overwrite
            // A chunk: 128 rows x 64 cols (hi + lo)
            #pragma unroll
            for (int i = 0; i < 4; i++) {
                int g = tid + i * 256;              // 0..1023 granules of 8 bf16
                int row = g >> 3, c8 = (g & 7) * 8;
                size_t soff = (size_t)(m0 + row) * KD + kc * 64 + c8;
                *(int4*)(As_hi + row * 72 + c8) = *(const int4*)(Ahi + soff);
                *(int4*)(As_lo + row * 72 + c8) = *(const int4*)(Alo + soff);
            }
            // B chunk: 64 h-rows x 64 cols (hi + lo)
            #pragma unroll
            for (int i = 0; i < 2; i++) {
                int g = tid + i * 256;              // 0..511
                int row = g >> 3, c8 = (g & 7) * 8;
                size_t soff = (size_t)(hc * 64 + row) * KD + kc * 64 + c8;
                *(int4*)(Bs_hi + row * 72 + c8) = *(const int4*)(Whi + soff);
                *(int4*)(Bs_lo + row * 72 + c8) = *(const int4*)(Wlo + soff);
            }
            __syncthreads();

            #pragma unroll
            for (int ks = 0; ks < 4; ks++) {
                wmma::fragment<wmma::matrix_a, 16, 16, 16, __nv_bfloat16, wmma::row_major> ah[2], al[2];
                wmma::fragment<wmma::matrix_b, 16, 16, 16, __nv_bfloat16, wmma::col_major> bh[2], bl[2];
                #pragma unroll
                for (int mi = 0; mi < 2; mi++) {
                    wmma::load_matrix_sync(ah[mi], As_hi + (m_off + 16 * mi) * 72 + ks * 16, 72);
                    wmma::load_matrix_sync(al[mi], As_lo + (m_off + 16 * mi) * 72 + ks * 16, 72);
                }
                #pragma unroll
                for (int ni = 0; ni < 2; ni++) {
                    wmma::load_matrix_sync(bh[ni], Bs_hi + (n_off + 16 * ni) * 72 + ks * 16, 72);
                    wmma::load_matrix_sync(bl[ni], Bs_lo + (n_off + 16 * ni) * 72 + ks * 16, 72);
                }
                #pragma unroll
                for (int mi = 0; mi < 2; mi++)
                    #pragma unroll
                    for (int ni = 0; ni < 2; ni++) {
                        wmma::mma_sync(acc[mi][ni], ah[mi], bh[ni], acc[mi][ni]);
                        wmma::mma_sync(acc[mi][ni], ah[mi], bl[ni], acc[mi][ni]);
                        wmma::mma_sync(acc[mi][ni], al[mi], bh[ni], acc[mi][ni]);
                    }
            }
        }

        // epilogue: D tile -> smem, tanh-dot with ys
        __syncthreads();
        #pragma unroll
        for (int mi = 0; mi < 2; mi++)
            #pragma unroll
            for (int ni = 0; ni < 2; ni++)
                wmma::store_matrix_sync(Ds + (m_off + 16 * mi) * 68 + n_off + 16 * ni,
                                        acc[mi][ni], 68, wmma::mem_row_major);
        __syncthreads();
        {
            int r = tid >> 1, ch = (tid & 1) * 32;
            const float* drow = Ds + r * 68 + ch;
            const float* yrow = ys + (r >> 4) * HH + hc * 64 + ch;
            float p = 0.0f;
            #pragma unroll
            for (int j = 0; j < 32; j++)
                p = fmaf(tanhf(drow[j]), yrow[j], p);
            wsacc += p;
        }
    }

    float other = __shfl_xor_sync(0xffffffffu, wsacc, 1);
    if ((tid & 1) == 0)
        ws[m0 + (tid >> 1)] = wsacc + other;
}

// ============================================================
// Generic fp32 tiled GEMM (unchanged from passing R5 kernel)
// ============================================================
template<bool TRANSB, bool TANH, bool BIASRELU>
__global__ void __launch_bounds__(256)
gemm_kernel(const float* __restrict__ A, const float* __restrict__ B,
            const float* __restrict__ bias, float* __restrict__ C,
            int M, int Nc, int Kc, int ldc, int coff)
{
    __shared__ float As[16][128];
    __shared__ float Bs[16][128];
    const int tid = threadIdx.x;
    const int tx = tid & 15, ty = tid >> 4;
    const int m0 = blockIdx.y * 128;
    const int n0 = blockIdx.x * 128;

    const int ar = tid >> 2;
    const int ac = (tid & 3) * 4;

    float acc[8][8] = {};

    for (int k0 = 0; k0 < Kc; k0 += 16) {
        #pragma unroll
        for (int r = 0; r < 2; r++) {
            int row = ar + r * 64;
            float4 v = *(const float4*)(A + (size_t)(m0 + row) * Kc + k0 + ac);
            As[ac + 0][row] = v.x; As[ac + 1][row] = v.y;
            As[ac + 2][row] = v.z; As[ac + 3][row] = v.w;
        }
        if (TRANSB) {
            #pragma unroll
            for (int r = 0; r < 2; r++) {
                int row = ar + r * 64;
                float4 v = *(const float4*)(B + (size_t)(n0 + row) * Kc + k0 + ac);
                Bs[ac + 0][row] = v.x; Bs[ac + 1][row] = v.y;
                Bs[ac + 2][row] = v.z; Bs[ac + 3][row] = v.w;
            }
        } else {
            int kr = tid >> 5;
            int nc = (tid & 31) * 4;
            #pragma unroll
            for (int r = 0; r < 2; r++) {
                int krr = kr + r * 8;
                float4 v = *(const float4*)(B + (size_t)(k0 + krr) * Nc + n0 + nc);
                *(float4*)&Bs[krr][nc] = v;
            }
        }
        __syncthreads();
        #pragma unroll
        for (int kk = 0; kk < 16; kk++) {
            float af[8], bf[8];
            *(float4*)&af[0] = *(const float4*)&As[kk][ty * 8];
            *(float4*)&af[4] = *(const float4*)&As[kk][ty * 8 + 4];
            *(float4*)&bf[0] = *(const float4*)&Bs[kk][tx * 8];
            *(float4*)&bf[4] = *(const float4*)&Bs[kk][tx * 8 + 4];
            #pragma unroll
            for (int i = 0; i < 8; i++)
                #pragma unroll
                for (int j = 0; j < 8; j++)
                    acc[i][j] = fmaf(af[i], bf[j], acc[i][j]);
        }
        __syncthreads();
    }

    #pragma unroll
    for (int i = 0; i < 8; i++) {
        int row = m0 + ty * 8 + i;
        #pragma unroll
        for (int jv = 0; jv < 2; jv++) {
            float4 v;
            float* vv = (float*)&v;
            #pragma unroll
            for (int j = 0; j < 4; j++) {
                int col = tx * 8 + jv * 4 + j;
                float val = acc[i][jv * 4 + j];
                if (TANH) val = tanhf(val);
                if (BIASRELU) { val += bias[n0 + col]; val = fmaxf(val, 0.0f); }
                vv[j] = val;
            }
            *(float4*)(C + (size_t)row * ldc + coff + n0 + tx * 8 + jv * 4) = v;
        }
    }
}

// ============================================================
// Softmax (scaled / masked) + weighted aggregation (unchanged)
// ============================================================
__global__ void __launch_bounds__(128)
softmax_agg(const float* __restrict__ wsn, const float* __restrict__ wse,
            const int* __restrict__ mask, const float* __restrict__ neibs,
            const float* __restrict__ edges,
            float* __restrict__ aggn, float* __restrict__ agge)
{
    const int n = blockIdx.x;
    const int tid = threadIdx.x;
    __shared__ float s1[16], s2[16];
    if (tid < 16) {
        s1[tid] = wsn[n * 16 + tid] * 0.04419417382415922f;  // 1/sqrt(512)
        s2[tid] = wse[n * 16 + tid] - 9999999.0f * (float)mask[n * 16 + tid];
    }
    __syncthreads();

    float w1[16], w2[16];
    float m1 = -1e30f, m2 = -1e30f;
    #pragma unroll
    for (int k = 0; k < 16; k++) {
        m1 = fmaxf(m1, s1[k]);
        m2 = fmaxf(m2, s2[k]);
    }
    float t1 = 0.0f, t2 = 0.0f;
    #pragma unroll
    for (int k = 0; k < 16; k++) {
        w1[k] = expf(s1[k] - m1); t1 += w1[k];
        w2[k] = expf(s2[k] - m2); t2 += w2[k];
    }
    const float r1 = 1.0f / t1, r2 = 1.0f / t2;

    #pragma unroll
    for (int p = 0; p < 2; p++) {
        int d = tid + p * 128;
        float acc = 0.0f;
        #pragma unroll
        for (int k = 0; k < 16; k++)
            acc = fmaf(w1[k], neibs[((size_t)n * 16 + k) * DD + d], acc);
        aggn[(size_t)n * DD + d] = acc * r1;
    }
    {
        int d = tid;
        float acc = 0.0f;
        #pragma unroll
        for (int k = 0; k < 16; k++)
            acc = fmaf(w2[k], edges[((size_t)n * 16 + k) * EE + d], acc);
        agge[(size_t)n * EE + d] = acc * r2;
    }
}

// ============================================================
extern "C" void kernel_launch(void* const* d_in, const int* in_sizes, int n_in,
                              void* d_out, int out_size)
{
    const float* x     = (const float*)d_in[0];
    const float* neibs = (const float*)d_in[1];
    const float* edge  = (const float*)d_in[2];
    const int*   mask  = (const int*)  d_in[3];
    const float* W1x   = (const float*)d_in[4];
    const float* W2x   = (const float*)d_in[5];
    const float* W1n   = (const float*)d_in[6];
    const float* W2n   = (const float*)d_in[7];
    const float* W1e   = (const float*)d_in[8];
    const float* W2e   = (const float*)d_in[9];
    const float* Wfx   = (const float*)d_in[10];
    const float* bfx   = (const float*)d_in[11];
    const float* Wfn   = (const float*)d_in[12];
    const float* bfn   = (const float*)d_in[13];
    const float* Wfe   = (const float*)d_in[14];
    const float* bfe   = (const float*)d_in[15];
    float* out = (float*)d_out;

    float *h1, *xatt, *yn, *ye, *wsn, *wse, *aggn, *agge;
    cudaGetSymbolAddress((void**)&h1,   g_h1);
    cudaGetSymbolAddress((void**)&xatt, g_xatt);
    cudaGetSymbolAddress((void**)&yn,   g_yn);
    cudaGetSymbolAddress((void**)&ye,   g_ye);
    cudaGetSymbolAddress((void**)&wsn,  g_wsn);
    cudaGetSymbolAddress((void**)&wse,  g_wse);
    cudaGetSymbolAddress((void**)&aggn, g_aggn);
    cudaGetSymbolAddress((void**)&agge, g_agge);

    __nv_bfloat16 *nhi, *nlo, *ehi, *elo, *w1nhi, *w1nlo, *w1ehi, *w1elo;
    cudaGetSymbolAddress((void**)&nhi,   g_nhi);
    cudaGetSymbolAddress((void**)&nlo,   g_nlo);
    cudaGetSymbolAddress((void**)&ehi,   g_ehi);
    cudaGetSymbolAddress((void**)&elo,   g_elo);
    cudaGetSymbolAddress((void**)&w1nhi, g_w1nhi);
    cudaGetSymbolAddress((void**)&w1nlo, g_w1nlo);
    cudaGetSymbolAddress((void**)&w1ehi, g_w1ehi);
    cudaGetSymbolAddress((void**)&w1elo, g_w1elo);

    cudaFuncSetAttribute(ws_mma<DD>, cudaFuncAttributeMaxDynamicSharedMemorySize, WS2_SMEM);
    cudaFuncSetAttribute(ws_mma<EE>, cudaFuncAttributeMaxDynamicSharedMemorySize, WS2_SMEM);

    dim3 blk(256);

    // bf16 hi/lo splits (independent of the gemm chain)
    {
        int n4;
        n4 = NN * KNB * DD / 4; split_kernel<<<(n4 + 255) / 256, 256>>>(neibs, nhi, nlo, n4);
        n4 = NN * KNB * EE / 4; split_kernel<<<(n4 + 255) / 256, 256>>>(edge,  ehi, elo, n4);
        n4 = HH * DD / 4;       split_kernel<<<(n4 + 255) / 256, 256>>>(W1n, w1nhi, w1nlo, n4);
        n4 = HH * EE / 4;       split_kernel<<<(n4 + 255) / 256, 256>>>(W1e, w1ehi, w1elo, n4);
    }

    // x_att pipeline (8192 rows)
    gemm_kernel<true,  true,  false><<<dim3(HH/128, NN/128), blk>>>(x,    W1x, nullptr, h1,   NN, HH, DD, HH, 0);
    gemm_kernel<true,  false, false><<<dim3(HH/128, NN/128), blk>>>(h1,   W2x, nullptr, xatt, NN, HH, HH, HH, 0);
    gemm_kernel<false, false, false><<<dim3(HH/128, NN/128), blk>>>(xatt, W2n, nullptr, yn,   NN, HH, HH, HH, 0);
    gemm_kernel<false, false, false><<<dim3(HH/128, NN/128), blk>>>(xatt, W2e, nullptr, ye,   NN, HH, HH, HH, 0);

    // attention logits on tensor cores (bf16 hi/lo 3-term via mma.sync)
    ws_mma<DD><<<(NN * KNB) / 128, blk, WS2_SMEM>>>(nhi, nlo, w1nhi, w1nlo, yn, wsn);
    ws_mma<EE><<<(NN * KNB) / 128, blk, WS2_SMEM>>>(ehi, elo, w1ehi, w1elo, ye, wse);

    // softmax + aggregation
    softmax_agg<<<NN, 128>>>(wsn, wse, mask, neibs, edge, aggn, agge);

    // final linears + bias + relu, strided into [8192, 768] output
    gemm_kernel<true, false, true><<<dim3(OO/128, NN/128), blk>>>(x,    Wfx, bfx, out, NN, OO, DD, 3*OO, 0);
    gemm_kernel<true, false, true><<<dim3(OO/128, NN/128), blk>>>(aggn, Wfn, bfn, out, NN, OO, DD, 3*OO, OO);
    gemm_kernel<true, false, true><<<dim3(OO/128, NN/128), blk>>>(agge, Wfe, bfe, out, NN, OO, EE, 3*OO, 2*OO);
}